// round 4
// baseline (speedup 1.0000x reference)
#include <cuda_runtime.h>

// Problem constants
#define TV      16384   // T * V
#define CTX     16      // T
#define VOCABSZ 1024    // V
#define NB      256     // batch
#define ROWS    8       // W rows per CTA

// out[b, j] = relu( bias[j] + sum_t W[j, x[b,t] + t*V] )
//
// Strategy: stream all of W exactly once (coalesced). One CTA handles ROWS
// consecutive rows of W and ALL 256 batches. Per row: stage the 64KB row in
// shared memory, each thread (one batch) gathers its 16 columns and
// accumulates. Final: each thread writes ROWS consecutive floats (sector-
// dense 32B stores) with bias + relu.
//
// NOTE: x is int32 on device (JAX default config downcasts int64 -> int32).

extern __shared__ float s_row[];   // TV floats = 64 KB dynamic smem

__global__ __launch_bounds__(256, 3)
void lr_gather_kernel(const int*   __restrict__ x,
                      const float* __restrict__ W,
                      const float* __restrict__ bias,
                      float*       __restrict__ out)
{
    const int tid = threadIdx.x;           // = batch index b (256 threads)
    const int j0  = blockIdx.x * ROWS;     // first W row for this CTA

    // Column indices for this batch: col[t] = x[b,t] + t*V
    int cols[CTX];
    const int* xb = x + tid * CTX;
    #pragma unroll
    for (int t = 0; t < CTX; t++)
        cols[t] = xb[t] + t * VOCABSZ;

    float acc[ROWS];

    #pragma unroll 1
    for (int r = 0; r < ROWS; r++) {
        // Cooperative coalesced stage of row (j0+r) into smem: 64 KB,
        // 256 threads x 16 float4 each.
        const float4* __restrict__ src =
            (const float4*)(W + (size_t)(j0 + r) * TV);
        float4* dst = (float4*)s_row;
        #pragma unroll
        for (int i = 0; i < TV / 4 / 256; i++)
            dst[tid + i * 256] = src[tid + i * 256];
        __syncthreads();

        // Gather 16 columns from the staged row
        float s = 0.f;
        #pragma unroll
        for (int t = 0; t < CTX; t++)
            s += s_row[cols[t]];
        acc[r] = s;
        __syncthreads();
    }

    // Epilogue: bias + relu, 2x float4 store (32B sector-dense per thread)
    size_t base = (size_t)tid * TV + j0;
    #pragma unroll
    for (int r = 0; r < ROWS; r += 4) {
        float4 bv = *(const float4*)(bias + j0 + r);
        float4 o;
        o.x = fmaxf(acc[r + 0] + bv.x, 0.f);
        o.y = fmaxf(acc[r + 1] + bv.y, 0.f);
        o.z = fmaxf(acc[r + 2] + bv.z, 0.f);
        o.w = fmaxf(acc[r + 3] + bv.w, 0.f);
        *(float4*)(out + base + r) = o;
    }
}

extern "C" void kernel_launch(void* const* d_in, const int* in_sizes, int n_in,
                              void* d_out, int out_size)
{
    // Identify inputs by element count (robust to ordering):
    //   x: 256*16 = 4096 (int32), W: 16384*16384 (f32), b: 16384 (f32)
    const int*   x    = nullptr;
    const float* W    = nullptr;
    const float* bias = nullptr;
    for (int i = 0; i < n_in; i++) {
        if (in_sizes[i] == NB * CTX)          x    = (const int*)d_in[i];
        else if (in_sizes[i] == TV)           bias = (const float*)d_in[i];
        else                                  W    = (const float*)d_in[i];
    }
    float* out = (float*)d_out;

    cudaFuncSetAttribute(lr_gather_kernel,
                         cudaFuncAttributeMaxDynamicSharedMemorySize,
                         TV * sizeof(float));

    dim3 grid(TV / ROWS);   // 2048 CTAs
    dim3 block(256);
    lr_gather_kernel<<<grid, block, TV * sizeof(float)>>>(x, W, bias, out);
}

// round 7
// speedup vs baseline: 1.0143x; 1.0143x over previous
#include <cuda_runtime.h>
#include <cstdint>

// Problem constants
#define TV        16384         // T * V
#define CTX       16            // T
#define VOCABSZ   1024          // V
#define NB        256           // batch
#define ROWS      16            // W rows per CTA
#define ROW_BYTES (TV * 4)      // 64 KB per W row

// out[b, j] = relu( bias[j] + sum_t W[j, x[b,t] + t*V] )
//
// HBM-bound streaming of W (1 GB, read exactly once). Double-buffered
// cp.async.bulk pipeline: while 256 threads gather row r from one 64KB smem
// buffer, the bulk-copy engine fills the other buffer with row r+2. This
// keeps DRAM reads in flight 100% of the time (the R4 kernel serialized
// stage/gather with syncthreads, capping DRAM duty at ~76%).

extern __shared__ float s_buf[];   // 2 * TV floats = 128 KB dynamic smem

__device__ __forceinline__ uint32_t smem_u32(const void* p) {
    return (uint32_t)__cvta_generic_to_shared(p);
}

__device__ __forceinline__ void bulk_load_row(uint32_t dst_smem,
                                              const float* src,
                                              uint32_t mbar) {
    asm volatile(
        "mbarrier.arrive.expect_tx.shared::cta.b64 _, [%0], %1;"
        :: "r"(mbar), "r"((uint32_t)ROW_BYTES) : "memory");
    asm volatile(
        "cp.async.bulk.shared::cluster.global.mbarrier::complete_tx::bytes "
        "[%0], [%1], %2, [%3];"
        :: "r"(dst_smem), "l"(src), "r"((uint32_t)ROW_BYTES), "r"(mbar)
        : "memory");
}

__device__ __forceinline__ void mbar_wait(uint32_t mbar, uint32_t phase) {
    asm volatile(
        "{\n\t"
        ".reg .pred P;\n\t"
        "WAIT_%=: mbarrier.try_wait.parity.acquire.cta.shared::cta.b64 P, [%0], %1, 0x989680;\n\t"
        "@P bra DONE_%=;\n\t"
        "bra WAIT_%=;\n\t"
        "DONE_%=:\n\t"
        "}"
        :: "r"(mbar), "r"(phase) : "memory");
}

__global__ __launch_bounds__(256, 1)
void lr_pipe_kernel(const int*   __restrict__ x,
                    const float* __restrict__ W,
                    const float* __restrict__ bias,
                    float*       __restrict__ out)
{
    __shared__ alignas(8) uint64_t mbar[2];
    const int tid = threadIdx.x;            // = batch index b
    const int j0  = blockIdx.x * ROWS;      // first W row for this CTA

    const uint32_t mb0 = smem_u32(&mbar[0]);
    const uint32_t mb1 = smem_u32(&mbar[1]);
    const uint32_t sb0 = smem_u32(s_buf);
    const uint32_t sb1 = smem_u32(s_buf + TV);

    if (tid == 0) {
        asm volatile("mbarrier.init.shared::cta.b64 [%0], 1;" :: "r"(mb0) : "memory");
        asm volatile("mbarrier.init.shared::cta.b64 [%0], 1;" :: "r"(mb1) : "memory");
        asm volatile("fence.proxy.async.shared::cta;" ::: "memory");
    }
    __syncthreads();

    // Prologue: start copies of rows j0 and j0+1 into the two buffers.
    if (tid == 0) {
        bulk_load_row(sb0, W + (size_t)(j0 + 0) * TV, mb0);
        bulk_load_row(sb1, W + (size_t)(j0 + 1) * TV, mb1);
    }

    // Column indices for this batch (overlaps with first row copy).
    // x is int32 on device (JAX default downcasts int64).
    int cols[CTX];
    {
        const int4* xb = (const int4*)(x + tid * CTX);
        #pragma unroll
        for (int q = 0; q < CTX / 4; q++) {
            int4 v = xb[q];
            cols[q * 4 + 0] = v.x + (q * 4 + 0) * VOCABSZ;
            cols[q * 4 + 1] = v.y + (q * 4 + 1) * VOCABSZ;
            cols[q * 4 + 2] = v.z + (q * 4 + 2) * VOCABSZ;
            cols[q * 4 + 3] = v.w + (q * 4 + 3) * VOCABSZ;
        }
    }

    float acc[ROWS];

    #pragma unroll 1
    for (int r = 0; r < ROWS; r++) {
        const int      buf   = r & 1;
        const uint32_t mb    = buf ? mb1 : mb0;
        const uint32_t phase = (r >> 1) & 1;    // parity of this buffer's use

        mbar_wait(mb, phase);

        const float* __restrict__ rowp = s_buf + buf * TV;
        float s = 0.f;
        #pragma unroll
        for (int t = 0; t < CTX; t++)
            s += rowp[cols[t]];
        acc[r] = s;

        __syncthreads();    // everyone done reading this buffer

        if (r + 2 < ROWS && tid == 0)
            bulk_load_row(buf ? sb1 : sb0, W + (size_t)(j0 + r + 2) * TV, mb);
    }

    // Epilogue: bias + relu, 4x float4 stores (sector-dense).
    size_t base = (size_t)tid * TV + j0;
    #pragma unroll
    for (int r = 0; r < ROWS; r += 4) {
        float4 bv = *(const float4*)(bias + j0 + r);
        float4 o;
        o.x = fmaxf(acc[r + 0] + bv.x, 0.f);
        o.y = fmaxf(acc[r + 1] + bv.y, 0.f);
        o.z = fmaxf(acc[r + 2] + bv.z, 0.f);
        o.w = fmaxf(acc[r + 3] + bv.w, 0.f);
        *(float4*)(out + base + r) = o;
    }
}

extern "C" void kernel_launch(void* const* d_in, const int* in_sizes, int n_in,
                              void* d_out, int out_size)
{
    // Identify inputs by element count:
    //   x: 256*16 = 4096 (int32), W: 16384*16384 (f32), b: 16384 (f32)
    const int*   x    = nullptr;
    const float* W    = nullptr;
    const float* bias = nullptr;
    for (int i = 0; i < n_in; i++) {
        if (in_sizes[i] == NB * CTX)          x    = (const int*)d_in[i];
        else if (in_sizes[i] == TV)           bias = (const float*)d_in[i];
        else                                  W    = (const float*)d_in[i];
    }
    float* out = (float*)d_out;

    cudaFuncSetAttribute(lr_pipe_kernel,
                         cudaFuncAttributeMaxDynamicSharedMemorySize,
                         2 * TV * sizeof(float));

    dim3 grid(TV / ROWS);   // 1024 CTAs, 16 rows each
    dim3 block(256);
    lr_pipe_kernel<<<grid, block, 2 * TV * sizeof(float)>>>(x, W, bias, out);
}

// round 8
// speedup vs baseline: 1.1032x; 1.0876x over previous
#include <cuda_runtime.h>
#include <cstdint>

// Problem constants
#define TV        16384         // T * V
#define CTX       16            // T
#define VOCABSZ   1024          // V
#define NB        256           // batch
#define ROWS      16            // W rows per CTA
#define NBUF      3             // pipeline depth (3 x 64KB = 192KB smem)
#define ROW_BYTES (TV * 4)      // 64 KB per W row

// out[b, j] = relu( bias[j] + sum_t W[j, x[b,t] + t*V] )
//
// HBM-bound streaming of W (1 GB, read exactly once). 3-stage
// cp.async.bulk pipeline: steady state keeps TWO 64KB row copies in flight
// per SM, hiding the issue/wait dead time and per-copy front latency that
// capped the 2-stage version at 77.6% DRAM duty.

extern __shared__ float s_buf[];   // NBUF * TV floats = 192 KB dynamic smem

__device__ __forceinline__ uint32_t smem_u32(const void* p) {
    return (uint32_t)__cvta_generic_to_shared(p);
}

__device__ __forceinline__ void bulk_load_row(uint32_t dst_smem,
                                              const float* src,
                                              uint32_t mbar) {
    asm volatile(
        "mbarrier.arrive.expect_tx.shared::cta.b64 _, [%0], %1;"
        :: "r"(mbar), "r"((uint32_t)ROW_BYTES) : "memory");
    asm volatile(
        "cp.async.bulk.shared::cluster.global.mbarrier::complete_tx::bytes "
        "[%0], [%1], %2, [%3];"
        :: "r"(dst_smem), "l"(src), "r"((uint32_t)ROW_BYTES), "r"(mbar)
        : "memory");
}

__device__ __forceinline__ void mbar_wait(uint32_t mbar, uint32_t phase) {
    asm volatile(
        "{\n\t"
        ".reg .pred P;\n\t"
        "WAIT_%=: mbarrier.try_wait.parity.acquire.cta.shared::cta.b64 P, [%0], %1, 0x989680;\n\t"
        "@P bra DONE_%=;\n\t"
        "bra WAIT_%=;\n\t"
        "DONE_%=:\n\t"
        "}"
        :: "r"(mbar), "r"(phase) : "memory");
}

__global__ __launch_bounds__(256, 1)
void lr_pipe3_kernel(const int*   __restrict__ x,
                     const float* __restrict__ W,
                     const float* __restrict__ bias,
                     float*       __restrict__ out)
{
    __shared__ alignas(8) uint64_t mbar[NBUF];
    const int tid = threadIdx.x;            // = batch index b
    const int j0  = blockIdx.x * ROWS;      // first W row for this CTA

    uint32_t mb[NBUF], sb[NBUF];
    #pragma unroll
    for (int i = 0; i < NBUF; i++) {
        mb[i] = smem_u32(&mbar[i]);
        sb[i] = smem_u32(s_buf + i * TV);
    }

    if (tid == 0) {
        #pragma unroll
        for (int i = 0; i < NBUF; i++)
            asm volatile("mbarrier.init.shared::cta.b64 [%0], 1;"
                         :: "r"(mb[i]) : "memory");
        asm volatile("fence.proxy.async.shared::cta;" ::: "memory");
    }
    __syncthreads();

    // Prologue: launch copies of the first NBUF rows.
    if (tid == 0) {
        #pragma unroll
        for (int i = 0; i < NBUF; i++)
            bulk_load_row(sb[i], W + (size_t)(j0 + i) * TV, mb[i]);
    }

    // Column indices for this batch (overlaps with prologue copies).
    // x is int32 on device (JAX default downcasts int64).
    int cols[CTX];
    {
        const int4* xb = (const int4*)(x + tid * CTX);
        #pragma unroll
        for (int q = 0; q < CTX / 4; q++) {
            int4 v = xb[q];
            cols[q * 4 + 0] = v.x + (q * 4 + 0) * VOCABSZ;
            cols[q * 4 + 1] = v.y + (q * 4 + 1) * VOCABSZ;
            cols[q * 4 + 2] = v.z + (q * 4 + 2) * VOCABSZ;
            cols[q * 4 + 3] = v.w + (q * 4 + 3) * VOCABSZ;
        }
    }

    float acc[ROWS];
    int buf = 0, phase = 0;    // phase of buffer `buf`'s next completion

    #pragma unroll 1
    for (int r = 0; r < ROWS; r++) {
        mbar_wait(mb[buf], phase);

        const float* __restrict__ rowp = s_buf + buf * TV;
        float s = 0.f;
        #pragma unroll
        for (int t = 0; t < CTX; t++)
            s += rowp[cols[t]];
        acc[r] = s;

        __syncthreads();    // everyone done reading this buffer

        if (r + NBUF < ROWS && tid == 0)
            bulk_load_row(sb[buf], W + (size_t)(j0 + r + NBUF) * TV, mb[buf]);

        if (++buf == NBUF) { buf = 0; phase ^= 1; }
    }

    // Epilogue: bias + relu, 4x float4 stores (sector-dense).
    size_t base = (size_t)tid * TV + j0;
    #pragma unroll
    for (int r = 0; r < ROWS; r += 4) {
        float4 bv = *(const float4*)(bias + j0 + r);
        float4 o;
        o.x = fmaxf(acc[r + 0] + bv.x, 0.f);
        o.y = fmaxf(acc[r + 1] + bv.y, 0.f);
        o.z = fmaxf(acc[r + 2] + bv.z, 0.f);
        o.w = fmaxf(acc[r + 3] + bv.w, 0.f);
        *(float4*)(out + base + r) = o;
    }
}

extern "C" void kernel_launch(void* const* d_in, const int* in_sizes, int n_in,
                              void* d_out, int out_size)
{
    // Identify inputs by element count:
    //   x: 256*16 = 4096 (int32), W: 16384*16384 (f32), b: 16384 (f32)
    const int*   x    = nullptr;
    const float* W    = nullptr;
    const float* bias = nullptr;
    for (int i = 0; i < n_in; i++) {
        if (in_sizes[i] == NB * CTX)          x    = (const int*)d_in[i];
        else if (in_sizes[i] == TV)           bias = (const float*)d_in[i];
        else                                  W    = (const float*)d_in[i];
    }
    float* out = (float*)d_out;

    cudaFuncSetAttribute(lr_pipe3_kernel,
                         cudaFuncAttributeMaxDynamicSharedMemorySize,
                         NBUF * TV * sizeof(float));

    dim3 grid(TV / ROWS);   // 1024 CTAs, 16 rows each
    dim3 block(256);
    lr_pipe3_kernel<<<grid, block, NBUF * TV * sizeof(float)>>>(x, W, bias, out);
}